// round 3
// baseline (speedup 1.0000x reference)
#include <cuda_runtime.h>
#include <cuda_bf16.h>

#define L  48
#define D  256
#define Hd 256
#define Ad 128

// ---- scratch (device globals; no allocations anywhere) ----
__device__ float g_qk[L * 256];        // cols [0,128): q, [128,256): k
__device__ float g_attn[L * L];        // softmax(scores), row-major
__device__ float g_Y[9][L * Hd];       // 8 relation-type GEMM outputs + X@W_root at [8]
__device__ float g_h[L * Hd];          // RGCN output
__device__ float g_T[Hd];              // (sum_i h_i) @ W_nbr

// local type t = sp_i*4 + sp_j*2 + dir  ->  global etype = 2*(sp_i*48+sp_j)+dir
__constant__ int c_etype[8] = {0, 1, 2, 3, 96, 97, 98, 99};

// ---------------- K1: q|k = X @ [Wq | Wk] ----------------
__global__ void k_qk(const float* __restrict__ X,
                     const float* __restrict__ Wq,
                     const float* __restrict__ Wk) {
    __shared__ float xs[D];
    int i = blockIdx.x, t = threadIdx.x;       // blockDim = 256
    xs[t] = X[i * D + t];
    __syncthreads();
    const float* W;
    int col;
    if (t < Ad) { W = Wq; col = t; }
    else        { W = Wk; col = t - Ad; }
    float acc = 0.f;
#pragma unroll 8
    for (int d = 0; d < D; d++)
        acc = fmaf(xs[d], W[d * Ad + col], acc);
    g_qk[i * 256 + t] = acc;
}

// ---------------- K2: 9 GEMMs [48,256]x[256,256] (8 relation types + root) ----
// grid (8, 2, 9): 8 column tiles of 32, 2 row tiles of 24, 9 weight matrices.
// block 256 = 32 cols x 8 row-groups, 3 rows per thread.
__global__ void k_gemm(const float* __restrict__ X,
                       const float* __restrict__ Wrel,
                       const float* __restrict__ Wroot) {
    __shared__ float xs[24 * D];               // 24 KB
    int z = blockIdx.z;
    const float* __restrict__ W =
        (z == 8) ? Wroot : (Wrel + (size_t)c_etype[z] * D * Hd);
    int row0 = blockIdx.y * 24;
    int tid = threadIdx.x;
    for (int idx = tid; idx < 24 * D; idx += 256)
        xs[idx] = X[row0 * D + idx];
    __syncthreads();

    int c  = blockIdx.x * 32 + (tid & 31);     // output column
    int rg = tid >> 5;                         // row group 0..7
    const float* x0 = &xs[(rg * 3 + 0) * D];
    const float* x1 = &xs[(rg * 3 + 1) * D];
    const float* x2 = &xs[(rg * 3 + 2) * D];
    float a0 = 0.f, a1 = 0.f, a2 = 0.f;
#pragma unroll 8
    for (int d = 0; d < D; d++) {
        float w = W[d * Hd + c];               // 128B coalesced per warp
        a0 = fmaf(x0[d], w, a0);               // shared broadcast, conflict-free
        a1 = fmaf(x1[d], w, a1);
        a2 = fmaf(x2[d], w, a2);
    }
    int r = row0 + rg * 3;
    g_Y[z][(r + 0) * Hd + c] = a0;
    g_Y[z][(r + 1) * Hd + c] = a1;
    g_Y[z][(r + 2) * Hd + c] = a2;
}

// ---------------- K3: scores[i,t] = v . tanh(q_i + k_t), row softmax --------
__global__ void k_attn(const float* __restrict__ v) {
    __shared__ float qs[Ad], vs[Ad], sc[L];
    int i = blockIdx.x, t = threadIdx.x;       // blockDim = 128
    qs[t] = g_qk[i * 256 + t];
    vs[t] = v[t];
    __syncthreads();

    float s = 0.f;
    if (t < L) {
        const float* krow = &g_qk[t * 256 + 128];
#pragma unroll 4
        for (int a = 0; a < Ad; a++)
            s += vs[a] * tanhf(qs[a] + krow[a]);
        sc[t] = s;
    }
    __syncthreads();

    float mx = -1e30f;
    for (int j = 0; j < L; j++) mx = fmaxf(mx, sc[j]);
    float e = (t < L) ? expf(s - mx) : 0.f;
    __syncthreads();
    if (t < L) sc[t] = e;
    __syncthreads();
    float sum = 0.f;
    for (int j = 0; j < L; j++) sum += sc[j];
    if (t < L) g_attn[i * L + t] = e / sum;
}

// ---------------- K4: h[j] = sum_i attn[i,j] * Y_{t(i,j)}[i] + Xroot[j] + b --
__global__ void k_h(const int* __restrict__ speaker,
                    const float* __restrict__ b_rgcn) {
    __shared__ int   sp[L];
    __shared__ float ac[L];                    // attention column j
    int j = blockIdx.x, c = threadIdx.x;       // blockDim = 256
    if (c < L) { sp[c] = speaker[c]; ac[c] = g_attn[c * L + j]; }
    __syncthreads();

    int spj2 = sp[j] * 2;
    float acc = 0.f;
#pragma unroll 8
    for (int i = 0; i < L; i++) {
        int t = sp[i] * 4 + spj2 + (i < j ? 0 : 1);
        acc = fmaf(ac[i], g_Y[t][i * Hd + c], acc);
    }
    g_h[j * Hd + c] = acc + g_Y[8][j * Hd + c] + b_rgcn[c];
}

// ---------------- K5: T = (sum_j h_j) @ W_nbr  (fully-connected graph) ------
__global__ void k_T(const float* __restrict__ Wnbr) {
    __shared__ float S[Hd];
    int c = threadIdx.x;                       // blockDim = 256
    float s = 0.f;
#pragma unroll 8
    for (int j = 0; j < L; j++) s += g_h[j * Hd + c];
    S[c] = s;
    __syncthreads();
    float acc = 0.f;
#pragma unroll 8
    for (int d = 0; d < Hd; d++)
        acc = fmaf(S[d], Wnbr[d * Hd + c], acc);
    g_T[c] = acc;
}

// ---------------- K6: out = h @ W_self + T + b_gcn --------------------------
__global__ void k_out(const float* __restrict__ Wself,
                      const float* __restrict__ b_gcn,
                      float* __restrict__ out) {
    __shared__ float hs[Hd];
    int j = blockIdx.x, g = threadIdx.x;       // blockDim = 256
    hs[g] = g_h[j * Hd + g];
    __syncthreads();
    float acc = b_gcn[g] + g_T[g];
#pragma unroll 8
    for (int d = 0; d < Hd; d++)
        acc = fmaf(hs[d], Wself[d * Hd + g], acc);
    out[j * Hd + g] = acc;
}

extern "C" void kernel_launch(void* const* d_in, const int* in_sizes, int n_in,
                              void* d_out, int out_size) {
    const float* X      = (const float*)d_in[0];
    const int*   spk    = (const int*)  d_in[1];
    const float* Wq     = (const float*)d_in[2];
    const float* Wk     = (const float*)d_in[3];
    const float* v      = (const float*)d_in[4];
    const float* Wrel   = (const float*)d_in[5];
    const float* Wroot  = (const float*)d_in[6];
    const float* b_rgcn = (const float*)d_in[7];
    const float* Wnbr   = (const float*)d_in[8];
    const float* Wself  = (const float*)d_in[9];
    const float* b_gcn  = (const float*)d_in[10];
    float* out = (float*)d_out;

    k_qk  <<<L, 256>>>(X, Wq, Wk);
    k_gemm<<<dim3(8, 2, 9), 256>>>(X, Wrel, Wroot);
    k_attn<<<L, 128>>>(v);
    k_h   <<<L, 256>>>(spk, b_rgcn);
    k_T   <<<1, 256>>>(Wnbr);
    k_out <<<L, 256>>>(Wself, b_gcn, out);
}

// round 6
// speedup vs baseline: 1.0044x; 1.0044x over previous
#include <cuda_runtime.h>
#include <cuda_bf16.h>

#define L  48
#define D  256
#define Hd 256
#define Ad 128

// ---- scratch (device globals; no allocations anywhere) ----
__device__ float g_qk[L * 256];      // cols [0,128): q, [128,256): k
__device__ float g_root[L * Hd];     // X @ W_root
__device__ float g_attn[L * L];      // softmax rows
__device__ float g_Z2[8 * L * Hd];   // Z_t[j][d], zero where sp_j mismatches t
__device__ float g_h[L * Hd];        // RGCN output (init + RED-accumulated)

// local t = sp_i*4 + sp_j*2 + dir  ->  global etype = 96*sp_i + 2*sp_j + dir
__constant__ int c_etype[8] = {0, 1, 2, 3, 96, 97, 98, 99};

__device__ __forceinline__ float ftanh(float x) {
    float y; asm("tanh.approx.f32 %0, %1;" : "=f"(y) : "f"(x)); return y;
}

// ---------------- K1: [q|k|root] = X @ [Wq|Wk|Wroot]  (512 cols) -----------
__global__ void k1(const float* __restrict__ X,  const float* __restrict__ Wq,
                   const float* __restrict__ Wk, const float* __restrict__ Wr) {
    __shared__ float xs[3 * D];
    int r0 = blockIdx.x * 3;                       // 16 row-tiles of 3
    int c  = blockIdx.y * 256 + threadIdx.x;       // 512 output columns
    for (int idx = threadIdx.x; idx < 3 * D; idx += 256)
        xs[idx] = X[r0 * D + idx];
    __syncthreads();

    const float* Wp; int stride;
    if (c < 128)      { Wp = Wq + c;         stride = Ad; }
    else if (c < 256) { Wp = Wk + (c - 128); stride = Ad; }
    else              { Wp = Wr + (c - 256); stride = Hd; }

    float a0 = 0.f, a1 = 0.f, a2 = 0.f;
#pragma unroll 8
    for (int d = 0; d < D; d++) {
        float w = Wp[(size_t)d * stride];
        a0 = fmaf(xs[d],         w, a0);
        a1 = fmaf(xs[D + d],     w, a1);
        a2 = fmaf(xs[2 * D + d], w, a2);
    }
    if (c < 256) {
        g_qk[(r0 + 0) * 256 + c] = a0;
        g_qk[(r0 + 1) * 256 + c] = a1;
        g_qk[(r0 + 2) * 256 + c] = a2;
    } else {
        int cc = c - 256;
        g_root[(r0 + 0) * Hd + cc] = a0;
        g_root[(r0 + 1) * Hd + cc] = a1;
        g_root[(r0 + 2) * Hd + cc] = a2;
    }
}

// ---------------- K2: scores[i,t] = v . tanh(q_i + k_t), row softmax --------
__global__ void k2(const float* __restrict__ v) {
    __shared__ float qs[128], vs[128], ks[48 * 129], sc[48], sp4[4 * 48], se[48];
    int i = blockIdx.x, tid = threadIdx.x;          // block 256
    if (tid < 128) { qs[tid] = g_qk[i * 256 + tid]; vs[tid] = v[tid]; }
    for (int idx = tid; idx < 48 * 128; idx += 256) {
        int u = idx >> 7, a = idx & 127;
        ks[u * 129 + a] = g_qk[u * 256 + 128 + a];  // pad-129 kills bank conflicts
    }
    __syncthreads();

    int s = tid >> 6, u = tid & 63;                 // 4 a-chunks x 64 (48 active) keys
    float ps = 0.f;
    if (u < 48) {
        const float* kk = &ks[u * 129 + s * 32];
        const float* qq = &qs[s * 32];
        const float* vv = &vs[s * 32];
#pragma unroll
        for (int a = 0; a < 32; a++)
            ps += vv[a] * ftanh(qq[a] + kk[a]);
        sp4[s * 48 + u] = ps;
    }
    __syncthreads();
    if (tid < 48)
        sc[tid] = sp4[tid] + sp4[48 + tid] + sp4[96 + tid] + sp4[144 + tid];
    __syncthreads();
    float e = 0.f;
    if (tid < 48) {
        float mx = sc[0];
#pragma unroll 8
        for (int j = 1; j < 48; j++) mx = fmaxf(mx, sc[j]);
        e = __expf(sc[tid] - mx);
        se[tid] = e;
    }
    __syncthreads();
    if (tid < 48) {
        float sum = 0.f;
#pragma unroll 8
        for (int j = 0; j < 48; j++) sum += se[j];
        g_attn[i * 48 + tid] = e / sum;
    }
}

// ---------------- K3a: Z_t[j] = sum_i a_t[i,j] X[i];  h init = root + b -----
__global__ void k3a(const float* __restrict__ X, const int* __restrict__ speaker,
                    const float* __restrict__ b_rgcn) {
    __shared__ float a[48];
    __shared__ int   sp[48];
    int j = blockIdx.x, d = threadIdx.x;            // block 256
    if (d < 48) { a[d] = g_attn[d * 48 + j]; sp[d] = speaker[d]; }
    __syncthreads();
    int spj = sp[j];

    float c0 = 0.f, c1 = 0.f, c2 = 0.f, c3 = 0.f;   // acc idx = sp_i*2 + dir
#pragma unroll 8
    for (int i = 0; i < 48; i++) {
        float p = a[i] * X[i * 256 + d];
        int tl = sp[i] * 2 + (i < j ? 0 : 1);
        c0 += (tl == 0) ? p : 0.f;
        c1 += (tl == 1) ? p : 0.f;
        c2 += (tl == 2) ? p : 0.f;
        c3 += (tl == 3) ? p : 0.f;
    }
    int o = j * 256 + d;
    int b = spj * 2, nb = (1 - spj) * 2;
    g_Z2[(b + 0) * 12288 + o] = c0;                 // t = sp_i*4 + sp_j*2 + dir
    g_Z2[(b + 1) * 12288 + o] = c1;
    g_Z2[(b + 4) * 12288 + o] = c2;
    g_Z2[(b + 5) * 12288 + o] = c3;
    g_Z2[(nb + 0) * 12288 + o] = 0.f;
    g_Z2[(nb + 1) * 12288 + o] = 0.f;
    g_Z2[(nb + 4) * 12288 + o] = 0.f;
    g_Z2[(nb + 5) * 12288 + o] = 0.f;
    g_h[o] = g_root[o] + b_rgcn[d];
}

// ---------------- K3b: h += Z_t @ W_t  (8 GEMMs, RED-accumulated) -----------
__global__ void k3b(const float* __restrict__ Wrel) {
    __shared__ float zs[24 * 256];                  // 24 KB
    int t = blockIdx.z;
    const float* __restrict__ W = Wrel + (size_t)c_etype[t] * D * Hd;
    int row0 = blockIdx.y * 24;
    for (int idx = threadIdx.x; idx < 24 * 256; idx += 256)
        zs[idx] = g_Z2[t * 12288 + row0 * 256 + idx];
    __syncthreads();

    int c  = blockIdx.x * 32 + (threadIdx.x & 31);
    int rg = threadIdx.x >> 5;
    const float* z0 = &zs[(rg * 3 + 0) * 256];
    const float* z1 = &zs[(rg * 3 + 1) * 256];
    const float* z2 = &zs[(rg * 3 + 2) * 256];
    float a0 = 0.f, a1 = 0.f, a2 = 0.f;
#pragma unroll 8
    for (int d = 0; d < 256; d++) {
        float w = W[d * Hd + c];                    // 128B coalesced per warp
        a0 = fmaf(z0[d], w, a0);
        a1 = fmaf(z1[d], w, a1);
        a2 = fmaf(z2[d], w, a2);
    }
    int r = row0 + rg * 3;
    atomicAdd(&g_h[(r + 0) * Hd + c], a0);
    atomicAdd(&g_h[(r + 1) * Hd + c], a1);
    atomicAdd(&g_h[(r + 2) * Hd + c], a2);
}

// ---------------- K4: out = h @ W_self + (sum_j h_j) @ W_nbr + b ------------
__global__ void k4(const float* __restrict__ Wnbr, const float* __restrict__ Wself,
                   const float* __restrict__ bg, float* __restrict__ out) {
    __shared__ float S[256], h0[256], h1[256];
    int j0 = blockIdx.x * 2, g = threadIdx.x;       // block 256, 24 blocks
    float s = 0.f;
#pragma unroll 8
    for (int jj = 0; jj < 48; jj++) s += g_h[jj * 256 + g];
    S[g]  = s;
    h0[g] = g_h[j0 * 256 + g];
    h1[g] = g_h[(j0 + 1) * 256 + g];
    __syncthreads();

    float t = 0.f, a0 = 0.f, a1 = 0.f;
#pragma unroll 4
    for (int d = 0; d < 256; d++) {
        float wn = Wnbr[d * Hd + g];
        float ws = Wself[d * Hd + g];
        t  = fmaf(S[d],  wn, t);
        a0 = fmaf(h0[d], ws, a0);
        a1 = fmaf(h1[d], ws, a1);
    }
    float b = bg[g];
    out[j0 * 256 + g]       = a0 + t + b;
    out[(j0 + 1) * 256 + g] = a1 + t + b;
}

extern "C" void kernel_launch(void* const* d_in, const int* in_sizes, int n_in,
                              void* d_out, int out_size) {
    const float* X      = (const float*)d_in[0];
    const int*   spk    = (const int*)  d_in[1];
    const float* Wq     = (const float*)d_in[2];
    const float* Wk     = (const float*)d_in[3];
    const float* v      = (const float*)d_in[4];
    const float* Wrel   = (const float*)d_in[5];
    const float* Wroot  = (const float*)d_in[6];
    const float* b_rgcn = (const float*)d_in[7];
    const float* Wnbr   = (const float*)d_in[8];
    const float* Wself  = (const float*)d_in[9];
    const float* b_gcn  = (const float*)d_in[10];
    float* out = (float*)d_out;

    k1 <<<dim3(16, 2),    256>>>(X, Wq, Wk, Wroot);
    k2 <<<48,             256>>>(v);
    k3a<<<48,             256>>>(X, spk, b_rgcn);
    k3b<<<dim3(8, 2, 8),  256>>>(Wrel);
    k4 <<<24,             256>>>(Wnbr, Wself, b_gcn, out);
}

// round 9
// speedup vs baseline: 1.4637x; 1.4573x over previous
#include <cuda_runtime.h>
#include <cuda_bf16.h>

#define L  48
#define D  256
#define Hd 256
#define Ad 128

// ---- scratch (device globals; no allocations anywhere) ----
__device__ float g_qkp[2][L * 256];   // split-K partials: cols [0,128)=q, [128,256)=k
__device__ float g_rootp[2][L * Hd];  // split-K partials of X @ W_root
__device__ float g_attn[L * L];       // softmax rows
__device__ float g_Z2[8 * L * Hd];    // Z_t[j][d], zero rows where sp_j mismatches t
__device__ float g_h[L * Hd];         // RGCN output (init in k3a, RED-accumulated in k3b)

// local t = sp_i*4 + sp_j*2 + dir  ->  global etype = 96*sp_i + 2*sp_j + dir
__constant__ int c_etype[8] = {0, 1, 2, 3, 96, 97, 98, 99};

__device__ __forceinline__ float ftanh(float x) {
    float y; asm("tanh.approx.f32 %0, %1;" : "=f"(y) : "f"(x)); return y;
}

// ---------------- K1: [q|k|root] = X @ [Wq|Wk|Wroot], split-K partials ------
// grid (16 rowtiles of 3, 2 k-outer). block 256 = 128 col-quads x 2 k-inner.
// Each thread: 3 rows x 4 cols micro-tile over a 64-deep K chunk (float4 W).
__global__ void k1(const float* __restrict__ X,  const float* __restrict__ Wq,
                   const float* __restrict__ Wk, const float* __restrict__ Wr) {
    __shared__ float xs[3 * 128];          // 3 rows x 128 k-chunk
    __shared__ float red[128 * 12];        // inner-split reduction
    int r0 = blockIdx.x * 3;
    int ko = blockIdx.y;                   // outer K half
    int tid = threadIdx.x;
    for (int idx = tid; idx < 3 * 128; idx += 256) {
        int rr = idx >> 7, dd = idx & 127;
        xs[idx] = X[(r0 + rr) * D + ko * 128 + dd];
    }
    __syncthreads();

    int q  = tid & 127;                    // col-quad id
    int ki = tid >> 7;                     // inner K half
    int c4 = q * 4;                        // first of 4 output cols (0..508)
    const float* Wb; int stride; int isroot = 0;
    if (c4 < 128)      { Wb = Wq + c4;           stride = Ad; }
    else if (c4 < 256) { Wb = Wk + (c4 - 128);   stride = Ad; }
    else               { Wb = Wr + (c4 - 256);   stride = Hd; isroot = 1; }
    Wb += (size_t)(ko * 128 + ki * 64) * stride;

    float4 a0 = {0,0,0,0}, a1 = {0,0,0,0}, a2 = {0,0,0,0};
    const float* x0 = &xs[0 * 128 + ki * 64];
    const float* x1 = &xs[1 * 128 + ki * 64];
    const float* x2 = &xs[2 * 128 + ki * 64];
#pragma unroll 8
    for (int d = 0; d < 64; d++) {
        float4 w = *(const float4*)&Wb[(size_t)d * stride];
        float v0 = x0[d], v1 = x1[d], v2 = x2[d];
        a0.x = fmaf(v0, w.x, a0.x); a0.y = fmaf(v0, w.y, a0.y);
        a0.z = fmaf(v0, w.z, a0.z); a0.w = fmaf(v0, w.w, a0.w);
        a1.x = fmaf(v1, w.x, a1.x); a1.y = fmaf(v1, w.y, a1.y);
        a1.z = fmaf(v1, w.z, a1.z); a1.w = fmaf(v1, w.w, a1.w);
        a2.x = fmaf(v2, w.x, a2.x); a2.y = fmaf(v2, w.y, a2.y);
        a2.z = fmaf(v2, w.z, a2.z); a2.w = fmaf(v2, w.w, a2.w);
    }
    if (ki == 1) {
        float* r = &red[q * 12];
        r[0]=a0.x; r[1]=a0.y; r[2]=a0.z; r[3]=a0.w;
        r[4]=a1.x; r[5]=a1.y; r[6]=a1.z; r[7]=a1.w;
        r[8]=a2.x; r[9]=a2.y; r[10]=a2.z; r[11]=a2.w;
    }
    __syncthreads();
    if (ki == 0) {
        const float* r = &red[q * 12];
        float o[12] = {a0.x+r[0], a0.y+r[1], a0.z+r[2], a0.w+r[3],
                       a1.x+r[4], a1.y+r[5], a1.z+r[6], a1.w+r[7],
                       a2.x+r[8], a2.y+r[9], a2.z+r[10], a2.w+r[11]};
        if (!isroot) {
            for (int rr = 0; rr < 3; rr++)
                for (int cc = 0; cc < 4; cc++)
                    g_qkp[ko][(r0 + rr) * 256 + c4 + cc] = o[rr * 4 + cc];
        } else {
            int cb = c4 - 256;
            for (int rr = 0; rr < 3; rr++)
                for (int cc = 0; cc < 4; cc++)
                    g_rootp[ko][(r0 + rr) * 256 + cb + cc] = o[rr * 4 + cc];
        }
    }
}

// ---------------- K2: scores[i,t] = v . tanh(q_i + k_t), row softmax --------
__global__ void k2(const float* __restrict__ v) {
    __shared__ float qs[128], vs[128], ks[48 * 129], sc[48], sp4[4 * 48], se[48];
    int i = blockIdx.x, tid = threadIdx.x;          // block 256
    if (tid < 128) {
        qs[tid] = g_qkp[0][i * 256 + tid] + g_qkp[1][i * 256 + tid];
        vs[tid] = v[tid];
    }
    for (int idx = tid; idx < 48 * 128; idx += 256) {
        int u = idx >> 7, a = idx & 127;
        ks[u * 129 + a] = g_qkp[0][u * 256 + 128 + a]
                        + g_qkp[1][u * 256 + 128 + a];
    }
    __syncthreads();

    int s = tid >> 6, u = tid & 63;                 // 4 a-chunks x 64 (48 active)
    float ps = 0.f;
    if (u < 48) {
        const float* kk = &ks[u * 129 + s * 32];
        const float* qq = &qs[s * 32];
        const float* vv = &vs[s * 32];
#pragma unroll
        for (int a = 0; a < 32; a++)
            ps += vv[a] * ftanh(qq[a] + kk[a]);
        sp4[s * 48 + u] = ps;
    }
    __syncthreads();
    if (tid < 48)
        sc[tid] = sp4[tid] + sp4[48 + tid] + sp4[96 + tid] + sp4[144 + tid];
    __syncthreads();
    float e = 0.f;
    if (tid < 48) {
        float mx = sc[0];
#pragma unroll 8
        for (int j = 1; j < 48; j++) mx = fmaxf(mx, sc[j]);
        e = __expf(sc[tid] - mx);
        se[tid] = e;
    }
    __syncthreads();
    if (tid < 48) {
        float sum = 0.f;
#pragma unroll 8
        for (int j = 0; j < 48; j++) sum += se[j];
        g_attn[i * 48 + tid] = e / sum;
    }
}

// ---------------- K3a: Z_t[j] = sum_i a_t[i,j] X[i];  h init = root + b -----
__global__ void k3a(const float* __restrict__ X, const int* __restrict__ speaker,
                    const float* __restrict__ b_rgcn) {
    __shared__ float a[48];
    __shared__ int   sp[48];
    int j = blockIdx.x, d = threadIdx.x;            // block 256
    if (d < 48) { a[d] = g_attn[d * 48 + j]; sp[d] = speaker[d]; }
    __syncthreads();
    int spj = sp[j];

    float c0 = 0.f, c1 = 0.f, c2 = 0.f, c3 = 0.f;   // acc idx = sp_i*2 + dir
#pragma unroll 8
    for (int i = 0; i < 48; i++) {
        float p = a[i] * X[i * 256 + d];
        int tl = sp[i] * 2 + (i < j ? 0 : 1);
        c0 += (tl == 0) ? p : 0.f;
        c1 += (tl == 1) ? p : 0.f;
        c2 += (tl == 2) ? p : 0.f;
        c3 += (tl == 3) ? p : 0.f;
    }
    int o = j * 256 + d;
    int b = spj * 2, nb = (1 - spj) * 2;
    g_Z2[(b + 0) * 12288 + o] = c0;                 // t = sp_i*4 + sp_j*2 + dir
    g_Z2[(b + 1) * 12288 + o] = c1;
    g_Z2[(b + 4) * 12288 + o] = c2;
    g_Z2[(b + 5) * 12288 + o] = c3;
    g_Z2[(nb + 0) * 12288 + o] = 0.f;
    g_Z2[(nb + 1) * 12288 + o] = 0.f;
    g_Z2[(nb + 4) * 12288 + o] = 0.f;
    g_Z2[(nb + 5) * 12288 + o] = 0.f;
    g_h[o] = g_rootp[0][o] + g_rootp[1][o] + b_rgcn[d];
}

// ---------------- K3b: h += Z_t @ W_t, split-K RED-accumulated --------------
// grid (4 rowtiles of 12, 8 ksplit of 32, 8 types). block 256 = 64 quads x 4 rg.
// Thread micro-tile: 3 rows x 4 cols, float4 W loads. Atomic adds predicated
// by speaker match (skips the structurally-zero half of Z rows).
__global__ void k3b(const float* __restrict__ Wrel, const int* __restrict__ speaker) {
    __shared__ float zs[12 * 32];
    __shared__ int   sp[12];
    int t   = blockIdx.z;
    int tb  = (t >> 1) & 1;                // sp_j bit of this type
    int row0 = blockIdx.x * 12;
    int d0   = blockIdx.y * 32;
    int tid = threadIdx.x;
    for (int idx = tid; idx < 12 * 32; idx += 256) {
        int rr = idx >> 5, dd = idx & 31;
        zs[idx] = g_Z2[t * 12288 + (row0 + rr) * 256 + d0 + dd];
    }
    if (tid < 12) sp[tid] = speaker[row0 + tid];
    __syncthreads();

    int cq = (tid & 63) * 4;               // 4 output cols
    int rg = tid >> 6;                     // row group -> rows rg*3..+2
    const float* W = Wrel + (size_t)c_etype[t] * 65536 + (size_t)d0 * 256 + cq;
    const float* z0 = &zs[(rg * 3 + 0) * 32];
    const float* z1 = &zs[(rg * 3 + 1) * 32];
    const float* z2 = &zs[(rg * 3 + 2) * 32];
    float4 a0 = {0,0,0,0}, a1 = {0,0,0,0}, a2 = {0,0,0,0};
#pragma unroll 8
    for (int d = 0; d < 32; d++) {
        float4 w = *(const float4*)&W[(size_t)d * 256];
        float v0 = z0[d], v1 = z1[d], v2 = z2[d];
        a0.x = fmaf(v0, w.x, a0.x); a0.y = fmaf(v0, w.y, a0.y);
        a0.z = fmaf(v0, w.z, a0.z); a0.w = fmaf(v0, w.w, a0.w);
        a1.x = fmaf(v1, w.x, a1.x); a1.y = fmaf(v1, w.y, a1.y);
        a1.z = fmaf(v1, w.z, a1.z); a1.w = fmaf(v1, w.w, a1.w);
        a2.x = fmaf(v2, w.x, a2.x); a2.y = fmaf(v2, w.y, a2.y);
        a2.z = fmaf(v2, w.z, a2.z); a2.w = fmaf(v2, w.w, a2.w);
    }
    int lr = rg * 3;
    if (sp[lr + 0] == tb) {
        float* p = &g_h[(row0 + lr + 0) * 256 + cq];
        atomicAdd(p+0, a0.x); atomicAdd(p+1, a0.y);
        atomicAdd(p+2, a0.z); atomicAdd(p+3, a0.w);
    }
    if (sp[lr + 1] == tb) {
        float* p = &g_h[(row0 + lr + 1) * 256 + cq];
        atomicAdd(p+0, a1.x); atomicAdd(p+1, a1.y);
        atomicAdd(p+2, a1.z); atomicAdd(p+3, a1.w);
    }
    if (sp[lr + 2] == tb) {
        float* p = &g_h[(row0 + lr + 2) * 256 + cq];
        atomicAdd(p+0, a2.x); atomicAdd(p+1, a2.y);
        atomicAdd(p+2, a2.z); atomicAdd(p+3, a2.w);
    }
}

// ---------------- K4: out = h @ W_self + (sum_j h_j) @ W_nbr + b ------------
// grid 24 (j pairs), block 512 = 256 cols x 2 K-halves, smem reduction.
__global__ void k4(const float* __restrict__ Wnbr, const float* __restrict__ Wself,
                   const float* __restrict__ bg, float* __restrict__ out) {
    __shared__ float Sp[2][256], S[256], hp[512], red[3][256];
    int tid = threadIdx.x;
    int c  = tid & 255, kh = tid >> 8;
    int j0 = blockIdx.x * 2;

    float s = 0.f;
#pragma unroll 8
    for (int jj = 0; jj < 24; jj++) s += g_h[(kh * 24 + jj) * 256 + c];
    Sp[kh][c] = s;
    hp[tid] = g_h[j0 * 256 + tid];          // rows j0 (0..255) and j0+1 (256..511)
    __syncthreads();
    if (kh == 0) S[c] = Sp[0][c] + Sp[1][c];
    __syncthreads();

    float t = 0.f, a0 = 0.f, a1 = 0.f;
    const float* wn = Wnbr  + (size_t)(kh * 128) * 256 + c;
    const float* ws = Wself + (size_t)(kh * 128) * 256 + c;
#pragma unroll 8
    for (int d = 0; d < 128; d++) {
        int dd = kh * 128 + d;
        float wnv = wn[(size_t)d * 256];
        float wsv = ws[(size_t)d * 256];
        t  = fmaf(S[dd],        wnv, t);
        a0 = fmaf(hp[dd],       wsv, a0);
        a1 = fmaf(hp[256 + dd], wsv, a1);
    }
    if (kh == 1) { red[0][c] = t; red[1][c] = a0; red[2][c] = a1; }
    __syncthreads();
    if (kh == 0) {
        float tt = t + red[0][c] + bg[c];
        out[j0 * 256 + c]       = a0 + red[1][c] + tt;
        out[(j0 + 1) * 256 + c] = a1 + red[2][c] + tt;
    }
}

extern "C" void kernel_launch(void* const* d_in, const int* in_sizes, int n_in,
                              void* d_out, int out_size) {
    const float* X      = (const float*)d_in[0];
    const int*   spk    = (const int*)  d_in[1];
    const float* Wq     = (const float*)d_in[2];
    const float* Wk     = (const float*)d_in[3];
    const float* v      = (const float*)d_in[4];
    const float* Wrel   = (const float*)d_in[5];
    const float* Wroot  = (const float*)d_in[6];
    const float* b_rgcn = (const float*)d_in[7];
    const float* Wnbr   = (const float*)d_in[8];
    const float* Wself  = (const float*)d_in[9];
    const float* b_gcn  = (const float*)d_in[10];
    float* out = (float*)d_out;

    k1 <<<dim3(16, 2),   256>>>(X, Wq, Wk, Wroot);
    k2 <<<48,            256>>>(v);
    k3a<<<48,            256>>>(X, spk, b_rgcn);
    k3b<<<dim3(4, 8, 8), 256>>>(Wrel, spk);
    k4 <<<24,            512>>>(Wnbr, Wself, b_gcn, out);
}

// round 10
// speedup vs baseline: 1.6440x; 1.1232x over previous
#include <cuda_runtime.h>
#include <cuda_bf16.h>

#define L  48
#define NB 132     // grid size; <=148 SMs -> all blocks co-resident (1 wave)

// ---- scratch (device globals; zero-init, no allocations) ----
__device__ float g_qkp[2][L * 256];   // split-K partials: [0,128)=q, [128,256)=k
__device__ float g_rootp[2][L * 256]; // split-K partials of X @ W_root
__device__ float g_attn[L * L];
__device__ float g_Z2[8 * L * 256];   // Z_t[j][d] (zero rows where sp_j mismatches)
__device__ float g_h[L * 256];
__device__ float g_op[4][L * 256];    // h @ W_self k-split partials
__device__ float g_Tp[4][256];        // (sum_j h_j) @ W_nbr k-split partials

// grid barrier state (count returns to 0 each barrier; gen is generation-relative,
// so it is correct across graph replays)
__device__ int g_bar_count;
__device__ volatile int g_bar_gen;

// local t = sp_i*4 + sp_j*2 + dir  ->  global etype = 96*sp_i + 2*sp_j + dir
__constant__ int c_etype[8] = {0, 1, 2, 3, 96, 97, 98, 99};

__device__ __forceinline__ float ftanh(float x) {
    float y; asm("tanh.approx.f32 %0, %1;" : "=f"(y) : "f"(x)); return y;
}

__device__ __forceinline__ void gsync() {
    __syncthreads();
    if (threadIdx.x == 0) {
        __threadfence();                       // release prior writes
        int gen = g_bar_gen;                   // read BEFORE arriving
        if (atomicAdd(&g_bar_count, 1) == NB - 1) {
            g_bar_count = 0;
            __threadfence();                   // reset visible before gen flip
            g_bar_gen = gen + 1;
        } else {
            while (g_bar_gen == gen) __nanosleep(32);
        }
        __threadfence();                       // acquire
    }
    __syncthreads();
}

__global__ void __launch_bounds__(256)
fused(const float* __restrict__ X,      const int*   __restrict__ speaker,
      const float* __restrict__ Wq,     const float* __restrict__ Wk,
      const float* __restrict__ v,      const float* __restrict__ Wrel,
      const float* __restrict__ Wr,     const float* __restrict__ b_rgcn,
      const float* __restrict__ Wnbr,   const float* __restrict__ Wself,
      const float* __restrict__ bg,     float*       __restrict__ out) {
    __shared__ float smem[6784];               // 26.5 KB, re-carved per phase
    int bid = blockIdx.x, tid = threadIdx.x;

    // ============ P1: [q|k|root] = X @ [Wq|Wk|Wroot], split-K partials ======
    // 128 blocks: 16 rowtiles(3) x 4 colslices(128) x 2 k-halves(128).
    if (bid < 128) {
        int rt = bid & 15, cs = (bid >> 4) & 3, ko = bid >> 6;
        float* xs  = smem;                     // [3][128]
        float* red = smem + 384;               // [128][3]
        for (int idx = tid; idx < 384; idx += 256) {
            int rr = idx >> 7, dd = idx & 127;
            xs[idx] = X[(rt * 3 + rr) * 256 + ko * 128 + dd];
        }
        __syncthreads();
        int cl = tid & 127, ki = tid >> 7;
        int c  = cs * 128 + cl;
        const float* Wb; int stride;
        if (c < 128)      { Wb = Wq + c;         stride = 128; }
        else if (c < 256) { Wb = Wk + (c - 128); stride = 128; }
        else              { Wb = Wr + (c - 256); stride = 256; }
        Wb += (size_t)(ko * 128 + ki * 64) * stride;
        const float *x0 = &xs[ki * 64], *x1 = &xs[128 + ki * 64], *x2 = &xs[256 + ki * 64];
        float a0 = 0.f, a1 = 0.f, a2 = 0.f;
#pragma unroll 8
        for (int d = 0; d < 64; d++) {
            float w = Wb[(size_t)d * stride];
            a0 = fmaf(x0[d], w, a0); a1 = fmaf(x1[d], w, a1); a2 = fmaf(x2[d], w, a2);
        }
        if (ki == 1) { red[cl * 3] = a0; red[cl * 3 + 1] = a1; red[cl * 3 + 2] = a2; }
        __syncthreads();
        if (ki == 0) {
            a0 += red[cl * 3]; a1 += red[cl * 3 + 1]; a2 += red[cl * 3 + 2];
            float* dst = (c < 256) ? &g_qkp[ko][0] : &g_rootp[ko][0];
            int cc = (c < 256) ? c : (c - 256);
            dst[(rt * 3 + 0) * 256 + cc] = a0;
            dst[(rt * 3 + 1) * 256 + cc] = a1;
            dst[(rt * 3 + 2) * 256 + cc] = a2;
        }
    }
    gsync();

    // ============ P2: scores[i,t] = v . tanh(q_i + k_t), row softmax ========
    if (bid < 48) {
        float* qs  = smem;            // 128
        float* vs  = smem + 128;      // 128
        float* ks  = smem + 256;      // 48*129
        float* sc  = smem + 6448;     // 48
        float* sp4 = smem + 6496;     // 192
        float* se  = smem + 6688;     // 48
        int i = bid;
        if (tid < 128) {
            qs[tid] = g_qkp[0][i * 256 + tid] + g_qkp[1][i * 256 + tid];
            vs[tid] = v[tid];
        }
        for (int idx = tid; idx < 48 * 128; idx += 256) {
            int u = idx >> 7, a = idx & 127;
            ks[u * 129 + a] = g_qkp[0][u * 256 + 128 + a]
                            + g_qkp[1][u * 256 + 128 + a];
        }
        __syncthreads();
        int s = tid >> 6, u = tid & 63;
        float ps = 0.f;
        if (u < 48) {
            const float *kk = &ks[u * 129 + s * 32], *qq = &qs[s * 32], *vv = &vs[s * 32];
#pragma unroll
            for (int a = 0; a < 32; a++) ps += vv[a] * ftanh(qq[a] + kk[a]);
            sp4[s * 48 + u] = ps;
        }
        __syncthreads();
        if (tid < 48)
            sc[tid] = sp4[tid] + sp4[48 + tid] + sp4[96 + tid] + sp4[144 + tid];
        __syncthreads();
        float e = 0.f;
        if (tid < 48) {
            float mx = sc[0];
#pragma unroll 8
            for (int j = 1; j < 48; j++) mx = fmaxf(mx, sc[j]);
            e = __expf(sc[tid] - mx);
            se[tid] = e;
        }
        __syncthreads();
        if (tid < 48) {
            float sum = 0.f;
#pragma unroll 8
            for (int j = 0; j < 48; j++) sum += se[j];
            g_attn[i * 48 + tid] = e / sum;
        }
    }
    gsync();

    // ============ P3: Z_t[j] = sum_i a_t[i,j] X[i];  h init = root + b ======
    if (bid < 48) {
        float* a  = smem;                      // 48
        int*   sp = (int*)(smem + 64);         // 48
        int j = bid, d = tid;
        if (d < 48) { a[d] = g_attn[d * 48 + j]; sp[d] = speaker[d]; }
        __syncthreads();
        int spj = sp[j];
        float c0 = 0.f, c1 = 0.f, c2 = 0.f, c3 = 0.f;
#pragma unroll 8
        for (int i = 0; i < 48; i++) {
            float p = a[i] * X[i * 256 + d];
            int tl = sp[i] * 2 + (i < j ? 0 : 1);
            c0 += (tl == 0) ? p : 0.f;
            c1 += (tl == 1) ? p : 0.f;
            c2 += (tl == 2) ? p : 0.f;
            c3 += (tl == 3) ? p : 0.f;
        }
        int o = j * 256 + d;
        int b = spj * 2, nb = (1 - spj) * 2;
        g_Z2[(b + 0) * 12288 + o] = c0;
        g_Z2[(b + 1) * 12288 + o] = c1;
        g_Z2[(b + 4) * 12288 + o] = c2;
        g_Z2[(b + 5) * 12288 + o] = c3;
        g_Z2[(nb + 0) * 12288 + o] = 0.f;
        g_Z2[(nb + 1) * 12288 + o] = 0.f;
        g_Z2[(nb + 4) * 12288 + o] = 0.f;
        g_Z2[(nb + 5) * 12288 + o] = 0.f;
        g_h[o] = g_rootp[0][o] + g_rootp[1][o] + b_rgcn[d];
    }
    gsync();

    // ============ P4: h += Z_t @ W_t (8 types x 8 ksplit x 2 rowtiles) ======
    // block: 24 rows x 256 cols, K=32. thread: 6 rows x 4 cols, float4 W.
    if (bid < 128) {
        int t  = bid & 7, ks = (bid >> 3) & 7, rt = bid >> 6;
        int tb = (t >> 1) & 1;                 // sp_j bit of this type
        int row0 = rt * 24, d0 = ks * 32;
        float* zs = smem;                      // [24][32]
        int*   sp = (int*)(smem + 768);        // 24
        for (int idx = tid; idx < 768; idx += 256) {
            int rr = idx >> 5, dd = idx & 31;
            zs[idx] = g_Z2[t * 12288 + (row0 + rr) * 256 + d0 + dd];
        }
        if (tid < 24) sp[tid] = speaker[row0 + tid];
        __syncthreads();
        int cq = (tid & 63) * 4, rg = tid >> 6;
        const float* W = Wrel + (size_t)c_etype[t] * 65536 + (size_t)d0 * 256 + cq;
        const float* z = &zs[rg * 6 * 32];
        float4 acc[6] = {{0,0,0,0},{0,0,0,0},{0,0,0,0},{0,0,0,0},{0,0,0,0},{0,0,0,0}};
#pragma unroll 4
        for (int d = 0; d < 32; d++) {
            float4 w = *(const float4*)&W[(size_t)d * 256];
#pragma unroll
            for (int r = 0; r < 6; r++) {
                float zv = z[r * 32 + d];
                acc[r].x = fmaf(zv, w.x, acc[r].x);
                acc[r].y = fmaf(zv, w.y, acc[r].y);
                acc[r].z = fmaf(zv, w.z, acc[r].z);
                acc[r].w = fmaf(zv, w.w, acc[r].w);
            }
        }
        int lr = rg * 6;
#pragma unroll
        for (int r = 0; r < 6; r++) {
            if (sp[lr + r] == tb) {
                float* p = &g_h[(row0 + lr + r) * 256 + cq];
                atomicAdd(p + 0, acc[r].x); atomicAdd(p + 1, acc[r].y);
                atomicAdd(p + 2, acc[r].z); atomicAdd(p + 3, acc[r].w);
            }
        }
    }
    gsync();

    // ============ P5: U = h @ W_self partials  +  T = (sum h) @ W_nbr =======
    if (bid < 128) {
        // 16 rowtiles(3) x 2 colhalves(128) x 4 ksplit(64); inner ki splits 32.
        int rt = bid & 15, cs = (bid >> 4) & 1, ks = bid >> 5;
        float* hs  = smem;                     // [3][64]
        float* red = smem + 192;               // [128][3]
        int r0 = rt * 3;
        for (int idx = tid; idx < 192; idx += 256) {
            int rr = idx >> 6, dd = idx & 63;
            hs[idx] = g_h[(r0 + rr) * 256 + ks * 64 + dd];
        }
        __syncthreads();
        int cl = tid & 127, ki = tid >> 7;
        int c  = cs * 128 + cl;
        const float* Wb = Wself + (size_t)(ks * 64 + ki * 32) * 256 + c;
        const float *h0 = &hs[ki * 32], *h1 = &hs[64 + ki * 32], *h2 = &hs[128 + ki * 32];
        float a0 = 0.f, a1 = 0.f, a2 = 0.f;
#pragma unroll 8
        for (int d = 0; d < 32; d++) {
            float w = Wb[(size_t)d * 256];
            a0 = fmaf(h0[d], w, a0); a1 = fmaf(h1[d], w, a1); a2 = fmaf(h2[d], w, a2);
        }
        if (ki == 1) { red[cl * 3] = a0; red[cl * 3 + 1] = a1; red[cl * 3 + 2] = a2; }
        __syncthreads();
        if (ki == 0) {
            g_op[ks][(r0 + 0) * 256 + c] = a0 + red[cl * 3];
            g_op[ks][(r0 + 1) * 256 + c] = a1 + red[cl * 3 + 1];
            g_op[ks][(r0 + 2) * 256 + c] = a2 + red[cl * 3 + 2];
        }
    } else {
        // blocks 128..131: T k-split partials over K chunk [b*64, b*64+64)
        int b = bid - 128;
        float* Ssc = smem;                     // [4][64]
        float* Sc  = smem + 256;               // [64]
        int dd = tid & 63, jg = tid >> 6;
        float s = 0.f;
#pragma unroll
        for (int j = jg * 12; j < jg * 12 + 12; j++)
            s += g_h[j * 256 + b * 64 + dd];
        Ssc[jg * 64 + dd] = s;
        __syncthreads();
        if (tid < 64) Sc[tid] = Ssc[tid] + Ssc[64 + tid] + Ssc[128 + tid] + Ssc[192 + tid];
        __syncthreads();
        float t = 0.f;
#pragma unroll 8
        for (int d = 0; d < 64; d++)
            t = fmaf(Sc[d], Wnbr[(size_t)(b * 64 + d) * 256 + tid], t);
        g_Tp[b][tid] = t;
    }
    gsync();

    // ============ P6: out = sum_k U_k + sum_k T_k + b ======================
    if (bid < 48) {
        int j = bid, c = tid, o = j * 256 + c;
        out[o] = g_op[0][o] + g_op[1][o] + g_op[2][o] + g_op[3][o]
               + g_Tp[0][c] + g_Tp[1][c] + g_Tp[2][c] + g_Tp[3][c] + bg[c];
    }
}

extern "C" void kernel_launch(void* const* d_in, const int* in_sizes, int n_in,
                              void* d_out, int out_size) {
    const float* X      = (const float*)d_in[0];
    const int*   spk    = (const int*)  d_in[1];
    const float* Wq     = (const float*)d_in[2];
    const float* Wk     = (const float*)d_in[3];
    const float* v      = (const float*)d_in[4];
    const float* Wrel   = (const float*)d_in[5];
    const float* Wroot  = (const float*)d_in[6];
    const float* b_rgcn = (const float*)d_in[7];
    const float* Wnbr   = (const float*)d_in[8];
    const float* Wself  = (const float*)d_in[9];
    const float* b_gcn  = (const float*)d_in[10];
    float* out = (float*)d_out;

    fused<<<NB, 256>>>(X, spk, Wq, Wk, v, Wrel, Wroot, b_rgcn, Wnbr, Wself,
                       b_gcn, out);
}